// round 7
// baseline (speedup 1.0000x reference)
#include <cuda_runtime.h>
#include <cuda_fp16.h>

#define NN    512
#define H     128
#define L     4
#define NRBF  50
#define TBL   1024
#define NMOL  16
#define JT    8     // target nodes per msg block
#define IS    8     // i-range splits
#define NT    4     // nodes per update block

// ---- scratch (static __device__, no allocation) ----
__device__ float4  g_geo[NN * NN];        // [j][i] = (t_or_-1, dirx, diry, dirz), t = d*TBL/5
__device__ __half2 g_tbl[L][TBL][H];      // (psi_l(idx), psi_l(idx+1)) per h
__device__ float   g_x[NN * H];
__device__ float   g_A[NN * H];           // x @ Wx + b1 (current layer)
__device__ float   g_S[NN * H];           // sum_i silu(pre[i,j])
__device__ float   g_deg[NN];             // # valid neighbors of j (layer-invariant)
__device__ float   g_pool[NMOL * H];
__device__ float   g_cntm[NMOL];

__device__ __forceinline__ float tanhf_approx(float x) {
    float t;
    asm("tanh.approx.f32 %0, %1;" : "=f"(t) : "f"(x));
    return t;
}
__device__ __forceinline__ float siluf(float v) {
    float s = 0.5f * v;
    return fmaf(s, tanhf_approx(s), s);
}

// pair geometry (block per j, thread per i) + exact degree via smem reduce.
// Also zeroes g_pool rows and g_cntm (consumed much later).
__global__ void k_geo(const float* __restrict__ pos) {
    int j = blockIdx.x, i = threadIdx.x;
    float px = pos[j * 3 + 0], py = pos[j * 3 + 1], pz = pos[j * 3 + 2];
    float dx = pos[i * 3 + 0] - px;
    float dy = pos[i * 3 + 1] - py;
    float dz = pos[i * 3 + 2] - pz;
    float d  = sqrtf(dx * dx + dy * dy + dz * dz);
    float inv = 1.0f / fmaxf(d, 1e-8f);
    bool valid = (d < 5.0f) && (i != j);
    float t = valid ? d * ((float)TBL / 5.0f) : -1.0f;
    g_geo[j * NN + i] = make_float4(t, dx * inv, dy * inv, dz * inv);

    __shared__ int cnt;
    if (i == 0) cnt = 0;
    __syncthreads();
    unsigned m = __ballot_sync(0xffffffffu, valid);
    if ((i & 31) == 0) atomicAdd(&cnt, __popc(m));
    __syncthreads();
    if (i == 0) g_deg[j] = (float)cnt;

    if (j < NMOL && i < H) g_pool[j * H + i] = 0.0f;
    if (j == 0 && i < NMOL) g_cntm[i] = 0.0f;
}

// psi tables, half2-interleaved (psi(idx), psi(idx+1))
__global__ void k_table(const float* __restrict__ msg_w1) {
    int idx = blockIdx.x;        // 0..TBL-1
    int l   = blockIdx.y;
    int h   = threadIdx.x;
    __shared__ float e0[NRBF], e1[NRBF];
    float g  = 5.0f / (float)TBL;
    float d0 = (float)idx * g;
    float d1 = (float)(idx + 1) * g;
    if (h < NRBF) {
        float c  = 5.0f * (float)h / (float)(NRBF - 1);
        float u0 = d0 - c, u1 = d1 - c;
        e0[h] = expf(-u0 * u0 * 50.0f);
        e1[h] = expf(-u1 * u1 * 50.0f);
    }
    __syncthreads();
    const float* Wr = msg_w1 + l * 181 * H + H * H;   // rows [H, H+50)
    float s0 = 0.0f, s1 = 0.0f;
#pragma unroll
    for (int k = 0; k < NRBF; k++) {
        float w = Wr[k * H + h];
        s0 = fmaf(e0[k], w, s0);
        s1 = fmaf(e1[k], w, s1);
    }
    g_tbl[l][idx][h] = __floats2half2_rn(s0, s1);
}

// layer-0 bootstrap: x = embed[clip(an)], A = x@Wx0 + b1_0, S = 0, count atoms/mol
__global__ void k_A0(const int* __restrict__ an, const float* __restrict__ embed,
                     const float* __restrict__ msg_w1, const float* __restrict__ msg_b1,
                     const int* __restrict__ batch) {
    int i = blockIdx.x, h = threadIdx.x;
    int a = an[i];
    a = a < 0 ? 0 : (a > 99 ? 99 : a);
    float xval = embed[a * H + h];
    g_x[i * H + h] = xval;
    __shared__ float xv[H];
    xv[h] = xval;
    __syncthreads();
    const float* Wx = msg_w1;            // layer 0, rows [0,H)
    float acc = msg_b1[h];
#pragma unroll 8
    for (int k = 0; k < H; k++)
        acc = fmaf(xv[k], Wx[k * H + h], acc);
    g_A[i * H + h] = acc;
    g_S[i * H + h] = 0.0f;
    if (h == 0) atomicAdd(&g_cntm[batch[i]], 1.0f);
}

// message pass: S[j,h] += silu(A[i,h] + psi(d)[h] + dir.Wd[:,h]) over valid i
__global__ void k_msg(const float* __restrict__ msg_w1, int l) {
    int j0 = blockIdx.x * JT;
    int i0 = blockIdx.y * (NN / IS);
    int h  = threadIdx.x;
    const float* Wd = msg_w1 + l * 181 * H + (H + NRBF) * H;
    float wd0 = Wd[0 * H + h], wd1 = Wd[1 * H + h], wd2 = Wd[2 * H + h];
    const __half2* __restrict__ tbl = &g_tbl[l][0][0];

    float acc[JT];
#pragma unroll
    for (int jj = 0; jj < JT; jj++) acc[jj] = 0.0f;

#pragma unroll 2
    for (int i = i0; i < i0 + NN / IS; i++) {
        float a = __ldg(&g_A[i * H + h]);
#pragma unroll
        for (int jj = 0; jj < JT; jj++) {
            float4 w = __ldg(&g_geo[(j0 + jj) * NN + i]);
            int   t0 = (int)w.x;                 // invalid: w.x=-1 -> t0=-1
            t0 = t0 < 0 ? 0 : t0;                // safe index
            float f  = w.x - (float)t0;
            float2 T = __half22float2(__ldg(&tbl[t0 * H + h]));
            float pre = fmaf(f, T.y - T.x, a + T.x);
            pre = fmaf(w.y, wd0, pre);
            pre = fmaf(w.z, wd1, pre);
            pre = fmaf(w.w, wd2, pre);
            float s  = (w.x >= 0.0f) ? 0.5f * pre : 0.0f;   // mask; tanh(0)=0
            float th = tanhf_approx(s);
            acc[jj] = fmaf(s, th, acc[jj] + s);             // += silu
        }
    }
#pragma unroll
    for (int jj = 0; jj < JT; jj++)
        atomicAdd(&g_S[(j0 + jj) * H + h], acc[jj]);
}

// aggr = S@W2 + deg*b2 ; x += silu([x,aggr]@U1+ub1)@U2+ub2 ;
// then either produce next layer's A (+S zero) or pool (last layer).
__global__ void k_upd(const float* __restrict__ msg_w1, const float* __restrict__ msg_b1,
                      const float* __restrict__ msg_w2, const float* __restrict__ msg_b2,
                      const float* __restrict__ upd_w1, const float* __restrict__ upd_b1,
                      const float* __restrict__ upd_w2, const float* __restrict__ upd_b2,
                      const int* __restrict__ batch, int l) {
    int j0 = blockIdx.x * NT;
    int h  = threadIdx.x;
    __shared__ float sv[NT][H], xv[NT][H], av[NT][H], hv[NT][H];
#pragma unroll
    for (int jj = 0; jj < NT; jj++) {
        sv[jj][h] = g_S[(j0 + jj) * H + h];
        xv[jj][h] = g_x[(j0 + jj) * H + h];
    }
    __syncthreads();
    {   // aggr = S @ W2 + deg * b2
        float b = msg_b2[l * H + h];
        float acc[NT];
#pragma unroll
        for (int jj = 0; jj < NT; jj++) acc[jj] = g_deg[j0 + jj] * b;
        const float* W2 = msg_w2 + l * H * H;
#pragma unroll 8
        for (int k = 0; k < H; k++) {
            float w = W2[k * H + h];
#pragma unroll
            for (int jj = 0; jj < NT; jj++) acc[jj] = fmaf(sv[jj][k], w, acc[jj]);
        }
#pragma unroll
        for (int jj = 0; jj < NT; jj++) av[jj][h] = acc[jj];
    }
    __syncthreads();
    {   // hv = silu([x, aggr] @ U1 + ub1)
        float acc[NT];
        float b = upd_b1[l * H + h];
#pragma unroll
        for (int jj = 0; jj < NT; jj++) acc[jj] = b;
        const float* U1 = upd_w1 + l * 2 * H * H;
#pragma unroll 8
        for (int k = 0; k < H; k++) {
            float w = U1[k * H + h];
#pragma unroll
            for (int jj = 0; jj < NT; jj++) acc[jj] = fmaf(xv[jj][k], w, acc[jj]);
        }
#pragma unroll 8
        for (int k = 0; k < H; k++) {
            float w = U1[(H + k) * H + h];
#pragma unroll
            for (int jj = 0; jj < NT; jj++) acc[jj] = fmaf(av[jj][k], w, acc[jj]);
        }
#pragma unroll
        for (int jj = 0; jj < NT; jj++) hv[jj][h] = siluf(acc[jj]);
    }
    __syncthreads();
    float xnew[NT];
    {   // x_new = x + hv @ U2 + ub2
        float acc[NT];
        float b = upd_b2[l * H + h];
#pragma unroll
        for (int jj = 0; jj < NT; jj++) acc[jj] = b;
        const float* U2 = upd_w2 + l * H * H;
#pragma unroll 8
        for (int k = 0; k < H; k++) {
            float w = U2[k * H + h];
#pragma unroll
            for (int jj = 0; jj < NT; jj++) acc[jj] = fmaf(hv[jj][k], w, acc[jj]);
        }
#pragma unroll
        for (int jj = 0; jj < NT; jj++) {
            xnew[jj] = xv[jj][h] + acc[jj];
            g_x[(j0 + jj) * H + h] = xnew[jj];
        }
    }
    __syncthreads();
    if (l + 1 < L) {
        // A_next = x_new @ Wx_{l+1} + b1_{l+1} ; zero S
#pragma unroll
        for (int jj = 0; jj < NT; jj++) sv[jj][h] = xnew[jj];
        __syncthreads();
        const float* Wx = msg_w1 + (l + 1) * 181 * H;
        float b = msg_b1[(l + 1) * H + h];
        float acc[NT];
#pragma unroll
        for (int jj = 0; jj < NT; jj++) acc[jj] = b;
#pragma unroll 8
        for (int k = 0; k < H; k++) {
            float w = Wx[k * H + h];
#pragma unroll
            for (int jj = 0; jj < NT; jj++) acc[jj] = fmaf(sv[jj][k], w, acc[jj]);
        }
#pragma unroll
        for (int jj = 0; jj < NT; jj++) {
            g_A[(j0 + jj) * H + h] = acc[jj];
            g_S[(j0 + jj) * H + h] = 0.0f;
        }
    } else {
        // last layer: pool directly
#pragma unroll
        for (int jj = 0; jj < NT; jj++) {
            int b = batch[j0 + jj];
            atomicAdd(&g_pool[b * H + h], xnew[jj]);
        }
    }
}

// mean + output MLP
__global__ void k_head(const float* __restrict__ ow1, const float* __restrict__ ob1,
                       const float* __restrict__ ow2, const float* __restrict__ ob2,
                       float* __restrict__ out) {
    int m = blockIdx.x, h = threadIdx.x;
    __shared__ float pv[H];
    __shared__ float hv[64];
    pv[h] = g_pool[m * H + h] / fmaxf(g_cntm[m], 1.0f);
    __syncthreads();
    if (h < 64) {
        float acc = ob1[h];
#pragma unroll 8
        for (int k = 0; k < H; k++) acc = fmaf(pv[k], ow1[k * 64 + h], acc);
        float s = 0.5f * acc;
        hv[h] = fmaf(s, tanhf_approx(s), s);
    }
    __syncthreads();
    if (h == 0) {
        float acc = ob2[0];
#pragma unroll
        for (int k = 0; k < 64; k++) acc = fmaf(hv[k], ow2[k], acc);
        out[m] = acc;
    }
}

extern "C" void kernel_launch(void* const* d_in, const int* in_sizes, int n_in,
                              void* d_out, int out_size) {
    const int*   an     = (const int*)  d_in[0];
    const float* pos    = (const float*)d_in[1];
    const int*   batch  = (const int*)  d_in[2];
    const float* embed  = (const float*)d_in[3];
    const float* msg_w1 = (const float*)d_in[4];
    const float* msg_b1 = (const float*)d_in[5];
    const float* msg_w2 = (const float*)d_in[6];
    const float* msg_b2 = (const float*)d_in[7];
    const float* upd_w1 = (const float*)d_in[8];
    const float* upd_b1 = (const float*)d_in[9];
    const float* upd_w2 = (const float*)d_in[10];
    const float* upd_b2 = (const float*)d_in[11];
    const float* ow1    = (const float*)d_in[12];
    const float* ob1    = (const float*)d_in[13];
    const float* ow2    = (const float*)d_in[14];
    const float* ob2    = (const float*)d_in[15];
    float* out = (float*)d_out;

    k_geo<<<NN, NN>>>(pos);
    k_table<<<dim3(TBL, L), H>>>(msg_w1);
    k_A0<<<NN, H>>>(an, embed, msg_w1, msg_b1, batch);
    for (int l = 0; l < L; l++) {
        k_msg<<<dim3(NN / JT, IS), H>>>(msg_w1, l);
        k_upd<<<NN / NT, H>>>(msg_w1, msg_b1, msg_w2, msg_b2,
                              upd_w1, upd_b1, upd_w2, upd_b2, batch, l);
    }
    k_head<<<NMOL, H>>>(ow1, ob1, ow2, ob2, out);
}

// round 8
// speedup vs baseline: 2.2715x; 2.2715x over previous
#include <cuda_runtime.h>
#include <cuda_fp16.h>

#define NN    512
#define H     128
#define L     4
#define NRBF  50
#define TBL   1024
#define NMOL  16
#define JT    8     // target nodes per msg block
#define IS    16    // i-range splits
#define CH    16    // i's per staged chunk (CH*JT = 128 = blockDim)
#define NT    2     // nodes per update block

// ---- scratch (static __device__, no allocation) ----
__device__ float4  g_geo[NN * NN];        // [j][i] = (t_or_-1, dirx, diry, dirz), t = d*TBL/5
__device__ __half2 g_tbl[L][TBL][H];      // (psi/2(idx), psi/2(idx+1)) per h  (pre-halved)
__device__ float   g_x[NN * H];
__device__ float   g_A[NN * H];           // 0.5*(x @ Wx + b1) (pre-halved)
__device__ float   g_S[NN * H];           // sum_i silu(pre[i,j])
__device__ float   g_deg[NN];             // # valid neighbors of j (layer-invariant)
__device__ float   g_pool[NMOL * H];
__device__ float   g_cntm[NMOL];

__device__ __forceinline__ float tanhf_approx(float x) {
    float t;
    asm("tanh.approx.f32 %0, %1;" : "=f"(t) : "f"(x));
    return t;
}
__device__ __forceinline__ float siluf(float v) {
    float s = 0.5f * v;
    return fmaf(s, tanhf_approx(s), s);
}

// pair geometry (block per j, thread per i) + exact degree via smem reduce.
__global__ void k_geo(const float* __restrict__ pos) {
    int j = blockIdx.x, i = threadIdx.x;
    float px = pos[j * 3 + 0], py = pos[j * 3 + 1], pz = pos[j * 3 + 2];
    float dx = pos[i * 3 + 0] - px;
    float dy = pos[i * 3 + 1] - py;
    float dz = pos[i * 3 + 2] - pz;
    float d  = sqrtf(dx * dx + dy * dy + dz * dz);
    float inv = 1.0f / fmaxf(d, 1e-8f);
    bool valid = (d < 5.0f) && (i != j);
    float t = valid ? d * ((float)TBL / 5.0f) : -1.0f;
    g_geo[j * NN + i] = make_float4(t, dx * inv, dy * inv, dz * inv);

    __shared__ int cnt;
    if (i == 0) cnt = 0;
    __syncthreads();
    unsigned m = __ballot_sync(0xffffffffu, valid);
    if ((i & 31) == 0) atomicAdd(&cnt, __popc(m));
    __syncthreads();
    if (i == 0) g_deg[j] = (float)cnt;

    if (j < NMOL && i < H) g_pool[j * H + i] = 0.0f;
    if (j == 0 && i < NMOL) g_cntm[i] = 0.0f;
}

// psi tables, half2-interleaved, PRE-HALVED: (psi(idx)/2, psi(idx+1)/2)
__global__ void k_table(const float* __restrict__ msg_w1) {
    int idx = blockIdx.x;        // 0..TBL-1
    int l   = blockIdx.y;
    int h   = threadIdx.x;
    __shared__ float e0[NRBF], e1[NRBF];
    float g  = 5.0f / (float)TBL;
    float d0 = (float)idx * g;
    float d1 = (float)(idx + 1) * g;
    if (h < NRBF) {
        float c  = 5.0f * (float)h / (float)(NRBF - 1);
        float u0 = d0 - c, u1 = d1 - c;
        e0[h] = expf(-u0 * u0 * 50.0f);
        e1[h] = expf(-u1 * u1 * 50.0f);
    }
    __syncthreads();
    const float* Wr = msg_w1 + l * 181 * H + H * H;   // rows [H, H+50)
    float s0 = 0.0f, s1 = 0.0f;
#pragma unroll
    for (int k = 0; k < NRBF; k++) {
        float w = Wr[k * H + h];
        s0 = fmaf(e0[k], w, s0);
        s1 = fmaf(e1[k], w, s1);
    }
    g_tbl[l][idx][h] = __floats2half2_rn(0.5f * s0, 0.5f * s1);
}

// layer-0 bootstrap: x = embed[clip(an)], A = 0.5*(x@Wx0 + b1_0), S = 0, count atoms/mol
__global__ void k_A0(const int* __restrict__ an, const float* __restrict__ embed,
                     const float* __restrict__ msg_w1, const float* __restrict__ msg_b1,
                     const int* __restrict__ batch) {
    int i = blockIdx.x, h = threadIdx.x;
    int a = an[i];
    a = a < 0 ? 0 : (a > 99 ? 99 : a);
    float xval = embed[a * H + h];
    g_x[i * H + h] = xval;
    __shared__ float xv[H];
    xv[h] = xval;
    __syncthreads();
    const float* Wx = msg_w1;            // layer 0, rows [0,H)
    float acc = msg_b1[h];
#pragma unroll 8
    for (int k = 0; k < H; k++)
        acc = fmaf(xv[k], Wx[k * H + h], acc);
    g_A[i * H + h] = 0.5f * acc;
    g_S[i * H + h] = 0.0f;
    if (h == 0) atomicAdd(&g_cntm[batch[i]], 1.0f);
}

// message pass: S[j,h] += silu(2*(A/2 + psi/2 + dir.Wd/2)) over valid i
// smem-staged geo + A; only the table load goes to L2 in the hot loop.
__global__ void __launch_bounds__(128, 8)
k_msg(const float* __restrict__ msg_w1, int l) {
    int j0 = blockIdx.x * JT;
    int i0 = blockIdx.y * (NN / IS);     // 32 i's per block
    int h  = threadIdx.x;
    const float* Wd = msg_w1 + l * 181 * H + (H + NRBF) * H;
    float wd0 = 0.5f * __ldg(&Wd[h]);
    float wd1 = 0.5f * __ldg(&Wd[H + h]);
    float wd2 = 0.5f * __ldg(&Wd[2 * H + h]);
    const __half2* __restrict__ tbl = &g_tbl[l][0][0];

    __shared__ float4 sg[JT * CH];       // [jj][ii]
    __shared__ float  sa[CH][H];

    float acc[JT];
#pragma unroll
    for (int jj = 0; jj < JT; jj++) acc[jj] = 0.0f;

    for (int c = 0; c < (NN / IS) / CH; c++) {   // 2 chunks
        int ibase = i0 + c * CH;
        {   // cooperative staging: 1 geo float4 + CH A values per thread
            int jj = h / CH, ii = h % CH;
            sg[h] = g_geo[(j0 + jj) * NN + ibase + ii];
#pragma unroll
            for (int ii2 = 0; ii2 < CH; ii2++)
                sa[ii2][h] = g_A[(ibase + ii2) * H + h];
        }
        __syncthreads();
        for (int ii = 0; ii < CH; ii++) {
            float a = sa[ii][h];
#pragma unroll
            for (int jj = 0; jj < JT; jj++) {
                float4 w = sg[jj * CH + ii];                // LDS.128 broadcast
                int   t0 = (int)w.x;
                t0 = t0 < 0 ? 0 : t0;
                float f  = w.x - (float)t0;
                float2 T = __half22float2(__ldg(&tbl[t0 * H + h]));
                float s = fmaf(f, T.y - T.x, a + T.x);      // already /2
                s = fmaf(w.y, wd0, s);
                s = fmaf(w.z, wd1, s);
                s = fmaf(w.w, wd2, s);
                s = (w.x >= 0.0f) ? s : 0.0f;               // mask
                acc[jj] = fmaf(s, tanhf_approx(s), acc[jj] + s);   // += silu
            }
        }
        __syncthreads();
    }
#pragma unroll
    for (int jj = 0; jj < JT; jj++)
        atomicAdd(&g_S[(j0 + jj) * H + h], acc[jj]);
}

// aggr = S@W2 + deg*b2 ; x += silu([x,aggr]@U1+ub1)@U2+ub2 ;
// then produce next layer's A (halved, + S zero) or pool (last layer).
__global__ void k_upd(const float* __restrict__ msg_w1, const float* __restrict__ msg_b1,
                      const float* __restrict__ msg_w2, const float* __restrict__ msg_b2,
                      const float* __restrict__ upd_w1, const float* __restrict__ upd_b1,
                      const float* __restrict__ upd_w2, const float* __restrict__ upd_b2,
                      const int* __restrict__ batch, int l) {
    int j0 = blockIdx.x * NT;
    int h  = threadIdx.x;
    __shared__ float sv[NT][H], xv[NT][H], av[NT][H], hv[NT][H];
#pragma unroll
    for (int jj = 0; jj < NT; jj++) {
        sv[jj][h] = g_S[(j0 + jj) * H + h];
        xv[jj][h] = g_x[(j0 + jj) * H + h];
    }
    __syncthreads();
    {   // aggr = S @ W2 + deg * b2
        float b = msg_b2[l * H + h];
        float acc[NT];
#pragma unroll
        for (int jj = 0; jj < NT; jj++) acc[jj] = g_deg[j0 + jj] * b;
        const float* W2 = msg_w2 + l * H * H;
#pragma unroll 8
        for (int k = 0; k < H; k++) {
            float w = W2[k * H + h];
#pragma unroll
            for (int jj = 0; jj < NT; jj++) acc[jj] = fmaf(sv[jj][k], w, acc[jj]);
        }
#pragma unroll
        for (int jj = 0; jj < NT; jj++) av[jj][h] = acc[jj];
    }
    __syncthreads();
    {   // hv = silu([x, aggr] @ U1 + ub1)
        float acc[NT];
        float b = upd_b1[l * H + h];
#pragma unroll
        for (int jj = 0; jj < NT; jj++) acc[jj] = b;
        const float* U1 = upd_w1 + l * 2 * H * H;
#pragma unroll 8
        for (int k = 0; k < H; k++) {
            float w = U1[k * H + h];
#pragma unroll
            for (int jj = 0; jj < NT; jj++) acc[jj] = fmaf(xv[jj][k], w, acc[jj]);
        }
#pragma unroll 8
        for (int k = 0; k < H; k++) {
            float w = U1[(H + k) * H + h];
#pragma unroll
            for (int jj = 0; jj < NT; jj++) acc[jj] = fmaf(av[jj][k], w, acc[jj]);
        }
#pragma unroll
        for (int jj = 0; jj < NT; jj++) hv[jj][h] = siluf(acc[jj]);
    }
    __syncthreads();
    float xnew[NT];
    {   // x_new = x + hv @ U2 + ub2
        float acc[NT];
        float b = upd_b2[l * H + h];
#pragma unroll
        for (int jj = 0; jj < NT; jj++) acc[jj] = b;
        const float* U2 = upd_w2 + l * H * H;
#pragma unroll 8
        for (int k = 0; k < H; k++) {
            float w = U2[k * H + h];
#pragma unroll
            for (int jj = 0; jj < NT; jj++) acc[jj] = fmaf(hv[jj][k], w, acc[jj]);
        }
#pragma unroll
        for (int jj = 0; jj < NT; jj++) {
            xnew[jj] = xv[jj][h] + acc[jj];
            g_x[(j0 + jj) * H + h] = xnew[jj];
        }
    }
    __syncthreads();
    if (l + 1 < L) {
        // A_next = 0.5*(x_new @ Wx_{l+1} + b1_{l+1}) ; zero S
#pragma unroll
        for (int jj = 0; jj < NT; jj++) sv[jj][h] = xnew[jj];
        __syncthreads();
        const float* Wx = msg_w1 + (l + 1) * 181 * H;
        float b = msg_b1[(l + 1) * H + h];
        float acc[NT];
#pragma unroll
        for (int jj = 0; jj < NT; jj++) acc[jj] = b;
#pragma unroll 8
        for (int k = 0; k < H; k++) {
            float w = Wx[k * H + h];
#pragma unroll
            for (int jj = 0; jj < NT; jj++) acc[jj] = fmaf(sv[jj][k], w, acc[jj]);
        }
#pragma unroll
        for (int jj = 0; jj < NT; jj++) {
            g_A[(j0 + jj) * H + h] = 0.5f * acc[jj];
            g_S[(j0 + jj) * H + h] = 0.0f;
        }
    } else {
        // last layer: pool directly
#pragma unroll
        for (int jj = 0; jj < NT; jj++) {
            int b = batch[j0 + jj];
            atomicAdd(&g_pool[b * H + h], xnew[jj]);
        }
    }
}

// mean + output MLP
__global__ void k_head(const float* __restrict__ ow1, const float* __restrict__ ob1,
                       const float* __restrict__ ow2, const float* __restrict__ ob2,
                       float* __restrict__ out) {
    int m = blockIdx.x, h = threadIdx.x;
    __shared__ float pv[H];
    __shared__ float hv[64];
    pv[h] = g_pool[m * H + h] / fmaxf(g_cntm[m], 1.0f);
    __syncthreads();
    if (h < 64) {
        float acc = ob1[h];
#pragma unroll 8
        for (int k = 0; k < H; k++) acc = fmaf(pv[k], ow1[k * 64 + h], acc);
        float s = 0.5f * acc;
        hv[h] = fmaf(s, tanhf_approx(s), s);
    }
    __syncthreads();
    if (h == 0) {
        float acc = ob2[0];
#pragma unroll
        for (int k = 0; k < 64; k++) acc = fmaf(hv[k], ow2[k], acc);
        out[m] = acc;
    }
}

extern "C" void kernel_launch(void* const* d_in, const int* in_sizes, int n_in,
                              void* d_out, int out_size) {
    const int*   an     = (const int*)  d_in[0];
    const float* pos    = (const float*)d_in[1];
    const int*   batch  = (const int*)  d_in[2];
    const float* embed  = (const float*)d_in[3];
    const float* msg_w1 = (const float*)d_in[4];
    const float* msg_b1 = (const float*)d_in[5];
    const float* msg_w2 = (const float*)d_in[6];
    const float* msg_b2 = (const float*)d_in[7];
    const float* upd_w1 = (const float*)d_in[8];
    const float* upd_b1 = (const float*)d_in[9];
    const float* upd_w2 = (const float*)d_in[10];
    const float* upd_b2 = (const float*)d_in[11];
    const float* ow1    = (const float*)d_in[12];
    const float* ob1    = (const float*)d_in[13];
    const float* ow2    = (const float*)d_in[14];
    const float* ob2    = (const float*)d_in[15];
    float* out = (float*)d_out;

    k_geo<<<NN, NN>>>(pos);
    k_table<<<dim3(TBL, L), H>>>(msg_w1);
    k_A0<<<NN, H>>>(an, embed, msg_w1, msg_b1, batch);
    for (int l = 0; l < L; l++) {
        k_msg<<<dim3(NN / JT, IS), H>>>(msg_w1, l);
        k_upd<<<NN / NT, H>>>(msg_w1, msg_b1, msg_w2, msg_b2,
                              upd_w1, upd_b1, upd_w2, upd_b2, batch, l);
    }
    k_head<<<NMOL, H>>>(ow1, ob1, ow2, ob2, out);
}

// round 9
// speedup vs baseline: 2.3256x; 1.0238x over previous
#include <cuda_runtime.h>
#include <cuda_fp16.h>

#define NN    512
#define H     128
#define L     4
#define NRBF  50
#define TBL   1024
#define NMOL  16
#define JT    8     // target nodes per msg block
#define IS    16    // i-range splits
#define CH    16    // i's per staged chunk (CH*JT = 128 = blockDim)
#define NT    4     // nodes per update block (2 per thread-half)

// ---- scratch (static __device__, no allocation) ----
__device__ float4  g_geo[NN * NN];        // [j][i] = (t_or_-1, dirx, diry, dirz), t = d*TBL/5
__device__ __half2 g_tbl[L][TBL][H];      // (psi/2(idx), psi/2(idx+1)) per h  (pre-halved)
__device__ float   g_x[NN * H];
__device__ float   g_A[NN * H];           // 0.5*(x @ Wx + b1) (pre-halved)
__device__ float   g_S[NN * H];           // sum_i silu(pre[i,j])
__device__ float   g_deg[NN];             // # valid neighbors of j (layer-invariant)
__device__ float   g_pool[NMOL * H];
__device__ float   g_cntm[NMOL];

__device__ __forceinline__ float tanhf_approx(float x) {
    float t;
    asm("tanh.approx.f32 %0, %1;" : "=f"(t) : "f"(x));
    return t;
}
__device__ __forceinline__ float siluf(float v) {
    float s = 0.5f * v;
    return fmaf(s, tanhf_approx(s), s);
}

// pair geometry (block per j, thread per i) + exact degree via smem reduce.
__global__ void k_geo(const float* __restrict__ pos) {
    int j = blockIdx.x, i = threadIdx.x;
    float px = pos[j * 3 + 0], py = pos[j * 3 + 1], pz = pos[j * 3 + 2];
    float dx = pos[i * 3 + 0] - px;
    float dy = pos[i * 3 + 1] - py;
    float dz = pos[i * 3 + 2] - pz;
    float d  = sqrtf(dx * dx + dy * dy + dz * dz);
    float inv = 1.0f / fmaxf(d, 1e-8f);
    bool valid = (d < 5.0f) && (i != j);
    float t = valid ? d * ((float)TBL / 5.0f) : -1.0f;
    g_geo[j * NN + i] = make_float4(t, dx * inv, dy * inv, dz * inv);

    __shared__ int cnt;
    if (i == 0) cnt = 0;
    __syncthreads();
    unsigned m = __ballot_sync(0xffffffffu, valid);
    if ((i & 31) == 0) atomicAdd(&cnt, __popc(m));
    __syncthreads();
    if (i == 0) g_deg[j] = (float)cnt;

    if (j < NMOL && i < H) g_pool[j * H + i] = 0.0f;
    if (j == 0 && i < NMOL) g_cntm[i] = 0.0f;
}

// psi tables, half2-interleaved, PRE-HALVED: (psi(idx)/2, psi(idx+1)/2)
__global__ void k_table(const float* __restrict__ msg_w1) {
    int idx = blockIdx.x;        // 0..TBL-1
    int l   = blockIdx.y;
    int h   = threadIdx.x;
    __shared__ float e0[NRBF], e1[NRBF];
    float g  = 5.0f / (float)TBL;
    float d0 = (float)idx * g;
    float d1 = (float)(idx + 1) * g;
    if (h < NRBF) {
        float c  = 5.0f * (float)h / (float)(NRBF - 1);
        float u0 = d0 - c, u1 = d1 - c;
        e0[h] = expf(-u0 * u0 * 50.0f);
        e1[h] = expf(-u1 * u1 * 50.0f);
    }
    __syncthreads();
    const float* Wr = msg_w1 + l * 181 * H + H * H;   // rows [H, H+50)
    float s0 = 0.0f, s1 = 0.0f;
#pragma unroll
    for (int k = 0; k < NRBF; k++) {
        float w = Wr[k * H + h];
        s0 = fmaf(e0[k], w, s0);
        s1 = fmaf(e1[k], w, s1);
    }
    g_tbl[l][idx][h] = __floats2half2_rn(0.5f * s0, 0.5f * s1);
}

// layer-0 bootstrap: x = embed[clip(an)], A = 0.5*(x@Wx0 + b1_0), S = 0, count atoms/mol
__global__ void k_A0(const int* __restrict__ an, const float* __restrict__ embed,
                     const float* __restrict__ msg_w1, const float* __restrict__ msg_b1,
                     const int* __restrict__ batch) {
    int i = blockIdx.x, h = threadIdx.x;
    int a = an[i];
    a = a < 0 ? 0 : (a > 99 ? 99 : a);
    float xval = embed[a * H + h];
    g_x[i * H + h] = xval;
    __shared__ float xv[H];
    xv[h] = xval;
    __syncthreads();
    const float* Wx = msg_w1;            // layer 0, rows [0,H)
    float acc = msg_b1[h];
#pragma unroll 8
    for (int k = 0; k < H; k++)
        acc = fmaf(xv[k], Wx[k * H + h], acc);
    g_A[i * H + h] = 0.5f * acc;
    g_S[i * H + h] = 0.0f;
    if (h == 0) atomicAdd(&g_cntm[batch[i]], 1.0f);
}

// message pass: smem-staged geo (with pre-resolved table offset + frac) + A.
// Pair-uniform branch skips the full body for invalid pairs (no divergence:
// every lane reads the same smem entry).
__global__ void __launch_bounds__(128, 8)
k_msg(const float* __restrict__ msg_w1, int l) {
    int j0 = blockIdx.x * JT;
    int i0 = blockIdx.y * (NN / IS);     // 32 i's per block
    int h  = threadIdx.x;
    const float* Wd = msg_w1 + l * 181 * H + (H + NRBF) * H;
    float wd0 = 0.5f * __ldg(&Wd[h]);
    float wd1 = 0.5f * __ldg(&Wd[H + h]);
    float wd2 = 0.5f * __ldg(&Wd[2 * H + h]);
    const __half2* __restrict__ tbl = &g_tbl[l][0][0] + h;   // per-thread base

    __shared__ float4 sg[JT * CH];       // (f_or_-1, dirx, diry, dirz)
    __shared__ int    soff[JT * CH];     // t0 * H
    __shared__ float  sa[CH][H];

    float acc[JT];
#pragma unroll
    for (int jj = 0; jj < JT; jj++) acc[jj] = 0.0f;

    for (int c = 0; c < (NN / IS) / CH; c++) {   // 2 chunks
        int ibase = i0 + c * CH;
        {   // cooperative staging: resolve per-pair uniform work ONCE
            int jj = h / CH, ii = h % CH;
            float4 w = g_geo[(j0 + jj) * NN + ibase + ii];
            int t0 = (int)w.x;
            t0 = t0 < 0 ? 0 : t0;
            float f = w.x - (float)t0;               // <0 iff invalid
            sg[h]   = make_float4(w.x < 0.0f ? -1.0f : f, w.y, w.z, w.w);
            soff[h] = t0 * H;
#pragma unroll
            for (int ii2 = 0; ii2 < CH; ii2++)
                sa[ii2][h] = g_A[(ibase + ii2) * H + h];
        }
        __syncthreads();
        for (int ii = 0; ii < CH; ii++) {
            float a = sa[ii][h];
#pragma unroll
            for (int jj = 0; jj < JT; jj++) {
                float4 w = sg[jj * CH + ii];             // uniform across block
                if (w.x >= 0.0f) {                       // pair-uniform: no divergence
                    int off = soff[jj * CH + ii];
                    float2 T = __half22float2(__ldg(tbl + off));
                    float s = fmaf(w.x, T.y - T.x, a + T.x);   // lerp (already /2)
                    s = fmaf(w.y, wd0, s);
                    s = fmaf(w.z, wd1, s);
                    s = fmaf(w.w, wd2, s);
                    acc[jj] = fmaf(s, tanhf_approx(s), acc[jj] + s);   // += silu
                }
            }
        }
        __syncthreads();
    }
#pragma unroll
    for (int jj = 0; jj < JT; jj++)
        atomicAdd(&g_S[(j0 + jj) * H + h], acc[jj]);
}

// aggr = S@W2 + deg*b2 ; x += silu([x,aggr]@U1+ub1)@U2+ub2 ;
// 256 threads: half 0 owns j-pair {0,1}, half 1 owns {2,3}. Weights read once
// per block (second half hits L1). Then next-layer A or pooling.
__global__ void __launch_bounds__(256)
k_upd(const float* __restrict__ msg_w1, const float* __restrict__ msg_b1,
      const float* __restrict__ msg_w2, const float* __restrict__ msg_b2,
      const float* __restrict__ upd_w1, const float* __restrict__ upd_b1,
      const float* __restrict__ upd_w2, const float* __restrict__ upd_b2,
      const int* __restrict__ batch, int l) {
    int j0  = blockIdx.x * NT;
    int tid = threadIdx.x;
    int jb  = (tid >> 7) * 2;     // 0 or 2
    int h   = tid & 127;
    __shared__ float sv[NT][H], xv[NT][H], av[NT][H], hs[NT][H];
    sv[jb    ][h] = g_S[(j0 + jb    ) * H + h];
    sv[jb + 1][h] = g_S[(j0 + jb + 1) * H + h];
    xv[jb    ][h] = g_x[(j0 + jb    ) * H + h];
    xv[jb + 1][h] = g_x[(j0 + jb + 1) * H + h];
    __syncthreads();
    {   // aggr = S @ W2 + deg * b2
        float b = msg_b2[l * H + h];
        float a0 = g_deg[j0 + jb] * b, a1 = g_deg[j0 + jb + 1] * b;
        const float* W2 = msg_w2 + l * H * H;
#pragma unroll 8
        for (int k = 0; k < H; k++) {
            float w = W2[k * H + h];
            a0 = fmaf(sv[jb][k], w, a0);
            a1 = fmaf(sv[jb + 1][k], w, a1);
        }
        av[jb][h] = a0; av[jb + 1][h] = a1;
    }
    __syncthreads();
    {   // hs = silu([x, aggr] @ U1 + ub1)
        float b = upd_b1[l * H + h];
        float a0 = b, a1 = b;
        const float* U1 = upd_w1 + l * 2 * H * H;
#pragma unroll 8
        for (int k = 0; k < H; k++) {
            float w = U1[k * H + h];
            a0 = fmaf(xv[jb][k], w, a0);
            a1 = fmaf(xv[jb + 1][k], w, a1);
        }
#pragma unroll 8
        for (int k = 0; k < H; k++) {
            float w = U1[(H + k) * H + h];
            a0 = fmaf(av[jb][k], w, a0);
            a1 = fmaf(av[jb + 1][k], w, a1);
        }
        hs[jb][h] = siluf(a0); hs[jb + 1][h] = siluf(a1);
    }
    __syncthreads();
    float xn0, xn1;
    {   // x_new = x + hs @ U2 + ub2
        float b = upd_b2[l * H + h];
        float a0 = b, a1 = b;
        const float* U2 = upd_w2 + l * H * H;
#pragma unroll 8
        for (int k = 0; k < H; k++) {
            float w = U2[k * H + h];
            a0 = fmaf(hs[jb][k], w, a0);
            a1 = fmaf(hs[jb + 1][k], w, a1);
        }
        xn0 = xv[jb][h] + a0;
        xn1 = xv[jb + 1][h] + a1;
        g_x[(j0 + jb    ) * H + h] = xn0;
        g_x[(j0 + jb + 1) * H + h] = xn1;
    }
    __syncthreads();
    if (l + 1 < L) {
        // A_next = 0.5*(x_new @ Wx_{l+1} + b1_{l+1}) ; zero S
        sv[jb][h] = xn0; sv[jb + 1][h] = xn1;
        __syncthreads();
        const float* Wx = msg_w1 + (l + 1) * 181 * H;
        float b = msg_b1[(l + 1) * H + h];
        float a0 = b, a1 = b;
#pragma unroll 8
        for (int k = 0; k < H; k++) {
            float w = Wx[k * H + h];
            a0 = fmaf(sv[jb][k], w, a0);
            a1 = fmaf(sv[jb + 1][k], w, a1);
        }
        g_A[(j0 + jb    ) * H + h] = 0.5f * a0;
        g_A[(j0 + jb + 1) * H + h] = 0.5f * a1;
        g_S[(j0 + jb    ) * H + h] = 0.0f;
        g_S[(j0 + jb + 1) * H + h] = 0.0f;
    } else {
        // last layer: pool directly
        atomicAdd(&g_pool[batch[j0 + jb    ] * H + h], xn0);
        atomicAdd(&g_pool[batch[j0 + jb + 1] * H + h], xn1);
    }
}

// mean + output MLP
__global__ void k_head(const float* __restrict__ ow1, const float* __restrict__ ob1,
                       const float* __restrict__ ow2, const float* __restrict__ ob2,
                       float* __restrict__ out) {
    int m = blockIdx.x, h = threadIdx.x;
    __shared__ float pv[H];
    __shared__ float hv[64];
    pv[h] = g_pool[m * H + h] / fmaxf(g_cntm[m], 1.0f);
    __syncthreads();
    if (h < 64) {
        float acc = ob1[h];
#pragma unroll 8
        for (int k = 0; k < H; k++) acc = fmaf(pv[k], ow1[k * 64 + h], acc);
        float s = 0.5f * acc;
        hv[h] = fmaf(s, tanhf_approx(s), s);
    }
    __syncthreads();
    if (h == 0) {
        float acc = ob2[0];
#pragma unroll
        for (int k = 0; k < 64; k++) acc = fmaf(hv[k], ow2[k], acc);
        out[m] = acc;
    }
}

extern "C" void kernel_launch(void* const* d_in, const int* in_sizes, int n_in,
                              void* d_out, int out_size) {
    const int*   an     = (const int*)  d_in[0];
    const float* pos    = (const float*)d_in[1];
    const int*   batch  = (const int*)  d_in[2];
    const float* embed  = (const float*)d_in[3];
    const float* msg_w1 = (const float*)d_in[4];
    const float* msg_b1 = (const float*)d_in[5];
    const float* msg_w2 = (const float*)d_in[6];
    const float* msg_b2 = (const float*)d_in[7];
    const float* upd_w1 = (const float*)d_in[8];
    const float* upd_b1 = (const float*)d_in[9];
    const float* upd_w2 = (const float*)d_in[10];
    const float* upd_b2 = (const float*)d_in[11];
    const float* ow1    = (const float*)d_in[12];
    const float* ob1    = (const float*)d_in[13];
    const float* ow2    = (const float*)d_in[14];
    const float* ob2    = (const float*)d_in[15];
    float* out = (float*)d_out;

    k_geo<<<NN, NN>>>(pos);
    k_table<<<dim3(TBL, L), H>>>(msg_w1);
    k_A0<<<NN, H>>>(an, embed, msg_w1, msg_b1, batch);
    for (int l = 0; l < L; l++) {
        k_msg<<<dim3(NN / JT, IS), H>>>(msg_w1, l);
        k_upd<<<NN / NT, 256>>>(msg_w1, msg_b1, msg_w2, msg_b2,
                                upd_w1, upd_b1, upd_w2, upd_b2, batch, l);
    }
    k_head<<<NMOL, H>>>(ow1, ob1, ow2, ob2, out);
}